// round 15
// baseline (speedup 1.0000x reference)
#include <cuda_runtime.h>
#include <cuda_fp16.h>
#include <cstdint>

#define N_PTS 200000
#define GRIDVOL (64*64*64)

// padded 66^3 flat grid + guard rows so every tap-shifted 514-row window
// stays in-bounds.
#define PXS 4356            // x stride (66*66)
#define PYS 66              // y stride
#define PTOT 287496         // 66^3
#define GUARD 4800
#define PROWS (PTOT + 2*GUARD)   // 297096
#define MTILE 512
#define NTILE2 562          // ceil(PTOT/512)
#define NTILE_M 1563        // ceil(N_PTS/128)

// conv smem (fp16): per buffer A 514*128 + W 3*8192
#define ABYTES 65792
#define WBYTES 24576
#define BUFBYTES (ABYTES + WBYTES)          // 90368
#define DSMEM_CONV (2 * BUFBYTES)           // 180736

// ---- scratch (allocation-free: __device__ globals, zero-initialized) ----
__device__ __half g_P[PROWS*64];          // conv1 input fp16: scatter target
                                          // (pre-scaled by pinv; pads stay 0)
__device__ __half g_Q[PROWS*64];          // conv2 input fp16 (pads stay 0)
__device__ __half g_h2p[PROWS*64];        // conv2 output fp16, padded
__device__ float g_mlp[N_PTS*64];         // point branch
__device__ __half g_W[2][27*64*64];       // weights [tap][cout][cin] fp16

// ---------------------------------------------------------------------------
// helpers
// ---------------------------------------------------------------------------
__device__ __forceinline__ uint32_t smem_u32(const void* p) {
    uint32_t a;
    asm("{ .reg .u64 t; cvta.to.shared.u64 t, %1; cvt.u32.u64 %0, t; }"
        : "=r"(a) : "l"(p));
    return a;
}
__device__ __forceinline__ void ldsm_x4(uint32_t* r, uint32_t a) {
    asm volatile("ldmatrix.sync.aligned.m8n8.x4.shared.b16 {%0,%1,%2,%3}, [%4];"
        : "=r"(r[0]), "=r"(r[1]), "=r"(r[2]), "=r"(r[3]) : "r"(a));
}
__device__ __forceinline__ void ldsm_x2(uint32_t* r, uint32_t a) {
    asm volatile("ldmatrix.sync.aligned.m8n8.x2.shared.b16 {%0,%1}, [%2];"
        : "=r"(r[0]), "=r"(r[1]) : "r"(a));
}
__device__ __forceinline__ void mma_f16(float* c, const uint32_t* a,
                                        const uint32_t* b) {
    asm volatile("mma.sync.aligned.m16n8k16.row.col.f32.f16.f16.f32 "
        "{%0,%1,%2,%3}, {%4,%5,%6,%7}, {%8,%9}, {%0,%1,%2,%3};"
        : "+f"(c[0]), "+f"(c[1]), "+f"(c[2]), "+f"(c[3])
        : "r"(a[0]), "r"(a[1]), "r"(a[2]), "r"(a[3]), "r"(b[0]), "r"(b[1]));
}
#define CP_ASYNC16(dst, src) \
    asm volatile("cp.async.cg.shared.global [%0], [%1], 16;" \
        :: "r"(dst), "l"(src) : "memory")
#define CP_COMMIT() asm volatile("cp.async.commit_group;" ::: "memory")
#define CP_WAIT(n)  asm volatile("cp.async.wait_group %0;" :: "n"(n) : "memory")

// ---------------------------------------------------------------------------
// voxelize fused: atomicAdd half2 of (in * pinv) directly into padded g_P.
// ---------------------------------------------------------------------------
__global__ void scatter_kernel(const float* __restrict__ in,
                               const int* __restrict__ vidx,
                               const float* __restrict__ pinv)
{
    int t = blockIdx.x * blockDim.x + threadIdx.x;
    if (t >= N_PTS * 32) return;
    int n = t >> 5, c2 = t & 31;
    int ix = vidx[n * 3 + 0];
    int iy = vidx[n * 3 + 1];
    int iz = vidx[n * 3 + 2];
    int vox = (((ix << 6) + iy) << 6) + iz;
    float s = pinv[vox];
    float2 v = ((const float2*)in)[n * 32 + c2];
    __half2 h;
    h.x = __float2half_rn(v.x * s);
    h.y = __float2half_rn(v.y * s);
    long p = (long)(ix + 1) * PXS + (iy + 1) * PYS + (iz + 1);
    atomicAdd((__half2*)&g_P[(GUARD + p) * 64 + c2 * 2], h);
}

// ---------------------------------------------------------------------------
// re-zero g_P's real-voxel region for the next graph replay
// ---------------------------------------------------------------------------
__global__ void zero_P_kernel() {
    float4* p = (float4*)&g_P[(long)GUARD * 64];
    const long n4 = (long)PTOT * 64 / 8;   // halfs -> float4 units
    for (long i = blockIdx.x * blockDim.x + threadIdx.x; i < n4;
         i += (long)gridDim.x * blockDim.x)
        p[i] = make_float4(0.f, 0.f, 0.f, 0.f);
}

// ---------------------------------------------------------------------------
// weight prep (both conv stages in one launch):
// k [tap][cin][cout] fp32 -> [tap][cout][cin] fp16
// ---------------------------------------------------------------------------
__global__ void build_W_kernel(const float* __restrict__ k1,
                               const float* __restrict__ k2) {
    int i = blockIdx.x * blockDim.x + threadIdx.x;
    const int n = 27 * 64 * 64;
    if (i >= 2 * n) return;
    int stage = (i >= n);
    int j = i - stage * n;
    const float* k = stage ? k2 : k1;
    int tap = j >> 12, r = j & 4095, cin = r >> 6, cout = r & 63;
    g_W[stage][(tap << 12) + (cout << 6) + cin] = __float2half_rn(k[j]);
}

// ---------------------------------------------------------------------------
// MLP as fp16 mma GEMM: CTA = 128 points x 64 couts, 8 warps (32x32 tiles)
// ---------------------------------------------------------------------------
__global__ __launch_bounds__(256) void mlp_mma_kernel(
    const float* __restrict__ in, const float* __restrict__ w,
    const float* __restrict__ b,
    const float* __restrict__ g0, const float* __restrict__ be0,
    const float* __restrict__ m0v, const float* __restrict__ v0)
{
    extern __shared__ char dyn[];
    __shared__ float s_ep[192];
    const int tid = threadIdx.x, lane = tid & 31, warp = tid >> 5;
    const int m0 = (warp >> 1) * 32, n0 = (warp & 1) * 32;
    const uint32_t S0 = smem_u32(dyn);

    if (tid < 64) {
        float sc = g0[tid] * rsqrtf(v0[tid] + 1e-3f);
        s_ep[tid] = b[tid];
        s_ep[64 + tid] = sc;
        s_ep[128 + tid] = be0[tid] - m0v[tid] * sc;
    }

    const float4* in4 = (const float4*)in;
    for (int i = tid; i < 2048; i += 256) {
        int row = i >> 4, c = i & 15;
        long n = (long)blockIdx.x * 128 + row;
        __half2 h0, h1;
        h0.x = h0.y = h1.x = h1.y = __float2half_rn(0.f);
        if (n < N_PTS) {
            float4 raw = in4[n * 16 + c];
            h0.x = __float2half_rn(raw.x); h0.y = __float2half_rn(raw.y);
            h1.x = __float2half_rn(raw.z); h1.y = __float2half_rn(raw.w);
        }
        uint32_t d = row * 128 + ((((uint32_t)(c >> 1)) ^ (row & 7)) << 4)
                     + (c & 1) * 8;
        *(__half2*)(dyn + d)     = h0;
        *(__half2*)(dyn + d + 4) = h1;
    }
    for (int i = tid; i < 4096; i += 256) {
        int ci = i >> 6, co = i & 63;
        uint32_t d = co * 128 + ((((uint32_t)(ci >> 3)) ^ (co & 7)) << 4)
                     + (ci & 7) * 2;
        *(__half*)(dyn + 16384 + d) = __float2half_rn(w[i]);
    }
    __syncthreads();

    float acc[2][4][4];
#pragma unroll
    for (int a = 0; a < 2; ++a)
#pragma unroll
        for (int x = 0; x < 4; ++x)
#pragma unroll
            for (int c = 0; c < 4; ++c) acc[a][x][c] = 0.f;

    const int arow = lane & 15, asel = lane >> 4;
    const int brow = lane & 7, bsel = (lane >> 3) & 1;
#pragma unroll
    for (int kc = 0; kc < 4; ++kc) {
        uint32_t af[2][4], bf[4][2];
#pragma unroll
        for (int mt = 0; mt < 2; ++mt) {
            int row = m0 + mt * 16 + arow;
            ldsm_x4(af[mt], S0 + row * 128 +
                    (((uint32_t)((kc * 2 + asel) ^ (row & 7))) << 4));
        }
#pragma unroll
        for (int nt = 0; nt < 4; ++nt) {
            int row = n0 + nt * 8 + brow;
            ldsm_x2(bf[nt], S0 + 16384 + row * 128 +
                    (((uint32_t)((kc * 2 + bsel) ^ (row & 7))) << 4));
        }
#pragma unroll
        for (int mt = 0; mt < 2; ++mt)
#pragma unroll
            for (int nt = 0; nt < 4; ++nt)
                mma_f16(acc[mt][nt], af[mt], bf[nt]);
    }

    const int gr = lane >> 2, tig = lane & 3;
#pragma unroll
    for (int mt = 0; mt < 2; ++mt)
#pragma unroll
        for (int half = 0; half < 2; ++half) {
            long n = (long)blockIdx.x * 128 + m0 + mt * 16 + half * 8 + gr;
            if (n >= N_PTS) continue;
#pragma unroll
            for (int nt = 0; nt < 4; ++nt) {
                int col = n0 + nt * 8 + tig * 2;
                float v0r = fmaxf(acc[mt][nt][half * 2 + 0] + s_ep[col], 0.f)
                            * s_ep[64 + col] + s_ep[128 + col];
                float v1r = fmaxf(acc[mt][nt][half * 2 + 1] + s_ep[col + 1], 0.f)
                            * s_ep[64 + col + 1] + s_ep[128 + col + 1];
                float2 fv; fv.x = v0r; fv.y = v1r;
                *(float2*)&g_mlp[n * 64 + col] = fv;
            }
        }
}

// ---------------------------------------------------------------------------
// Pipelined fp16 mma implicit-GEMM conv.
// CTA = 512 padded rows x 64 couts, 8 warps (256 threads), warp tile 64x64.
// Fragment double-buffering + W loaded via ldsm_x4 (4 instr instead of 8).
// Single barrier per stage: CP_WAIT(0) -> barrier -> issue s+1 -> compute s.
// buffer: A [0, 65792) (514 rows x 128B swizzled), W [65792 + dz*8192)
// ---------------------------------------------------------------------------
template<int STAGE>
__device__ __forceinline__ void conv_stage_async(
    uint32_t Sbuf, const __half* __restrict__ SRC,
    const uint4* __restrict__ Wsrc, long blockbase, int s, int tid)
{
    const int dx = s / 3, dy = s % 3, tap0 = s * 3;
    const long w0 = (long)GUARD + blockbase
                    + (long)(dx - 1) * PXS + (dy - 1) * PYS - 1;
    const uint4* asrc = (const uint4*)SRC + w0 * 8;
    for (int i = tid; i < 4112; i += 256) {
        int row = i >> 3, c = i & 7;
        uint32_t d = Sbuf + row * 128 + (((uint32_t)(c ^ (row & 7))) << 4);
        CP_ASYNC16(d, asrc + i);
    }
    for (int i = tid; i < 1536; i += 256) {
        int t3 = i >> 9, r = (i >> 3) & 63, c = i & 7;
        uint32_t d = Sbuf + ABYTES + t3 * 8192 + r * 128 +
                     (((uint32_t)(c ^ (r & 7))) << 4);
        CP_ASYNC16(d, Wsrc + (tap0 + t3) * 512 + r * 8 + c);
    }
}

template<int STAGE>
__global__ __launch_bounds__(256, 1) void conv_mma_kernel(
    const float* __restrict__ cb, const float* __restrict__ g,
    const float* __restrict__ be, const float* __restrict__ m,
    const float* __restrict__ v)
{
    extern __shared__ char dyn[];
    __shared__ float s_ep[192];
    const int tid = threadIdx.x, lane = tid & 31, warp = tid >> 5;
    const int m0 = warp * 64;   // 8 m-groups of 64 rows, full 64 couts
    const uint32_t S0 = smem_u32(dyn);

    if (tid < 64) {
        float sc = g[tid] * rsqrtf(v[tid] + 1e-3f);
        s_ep[tid] = cb[tid];
        s_ep[64 + tid] = sc;
        s_ep[128 + tid] = be[tid] - m[tid] * sc;
    }

    const __half* __restrict__ SRC = (STAGE == 1) ? g_P : g_Q;
    const uint4* __restrict__ Wsrc = (const uint4*)g_W[STAGE - 1];
    const long blockbase = (long)blockIdx.x * MTILE;

    float acc[4][8][4];
#pragma unroll
    for (int a = 0; a < 4; ++a)
#pragma unroll
        for (int x = 0; x < 8; ++x)
#pragma unroll
            for (int c = 0; c < 4; ++c) acc[a][x][c] = 0.f;

    const int arow = lane & 15, asel = lane >> 4;
    // W x4 ldsm lane mapping: quad q = lane>>3 -> (nt offset, k-half)
    const int bq = lane >> 3;
    const int bnt_off = bq >> 1;        // 0 or 1 within the nt pair
    const int bks = bq & 1;             // k-half select
    const int brow8 = lane & 7;

    conv_stage_async<STAGE>(S0, SRC, Wsrc, blockbase, 0, tid);
    CP_COMMIT();

    uint32_t afb[2][4][4], bfb[2][8][2];

    for (int s = 0; s < 9; ++s) {
        CP_WAIT(0);          // own stage-s copies arrived
        __syncthreads();     // publishes stage-s data; frees buffer (s+1)&1
        if (s < 8) {
            conv_stage_async<STAGE>(S0 + ((s + 1) & 1) * BUFBYTES, SRC, Wsrc,
                                    blockbase, s + 1, tid);
            CP_COMMIT();
        }

        const uint32_t SA = S0 + (s & 1) * BUFBYTES;
        const uint32_t SW = SA + ABYTES;

        // prologue fragment load: iteration 0 (dz=0, kc=0)
#pragma unroll
        for (int mt = 0; mt < 4; ++mt) {
            int row = 0 + m0 + mt * 16 + arow;
            ldsm_x4(afb[0][mt], SA + row * 128 +
                    (((uint32_t)((0 * 2 + asel) ^ (row & 7))) << 4));
        }
#pragma unroll
        for (int np = 0; np < 4; ++np) {
            int row = (np * 2 + bnt_off) * 8 + brow8;
            ldsm_x4(&bfb[0][np * 2][0], SW + 0 * 8192 + row * 128 +
                    (((uint32_t)((0 * 2 + bks) ^ (row & 7))) << 4));
        }

#pragma unroll
        for (int it = 0; it < 12; ++it) {
            const int cur = it & 1;
            if (it < 11) {
                const int nit = it + 1;
                const int ndz = nit >> 2, nkc = nit & 3;
                const int nxt = nit & 1;
#pragma unroll
                for (int mt = 0; mt < 4; ++mt) {
                    int row = ndz + m0 + mt * 16 + arow;
                    ldsm_x4(afb[nxt][mt], SA + row * 128 +
                            (((uint32_t)((nkc * 2 + asel) ^ (row & 7))) << 4));
                }
#pragma unroll
                for (int np = 0; np < 4; ++np) {
                    int row = (np * 2 + bnt_off) * 8 + brow8;
                    ldsm_x4(&bfb[nxt][np * 2][0], SW + ndz * 8192 + row * 128 +
                            (((uint32_t)((nkc * 2 + bks) ^ (row & 7))) << 4));
                }
            }
#pragma unroll
            for (int mt = 0; mt < 4; ++mt)
#pragma unroll
                for (int nt = 0; nt < 8; ++nt)
                    mma_f16(acc[mt][nt], afb[cur][mt], bfb[cur][nt]);
        }
    }

    // ---- epilogue: bias + relu + BN ----
    const int gr = lane >> 2, tig = lane & 3;
#pragma unroll
    for (int mt = 0; mt < 4; ++mt)
#pragma unroll
        for (int half = 0; half < 2; ++half) {
            int rl = m0 + mt * 16 + half * 8 + gr;
            long p = blockbase + rl;
            if (p >= PTOT) continue;
            if (STAGE == 1) {
                int x = (int)(p / PXS);
                int rem = (int)(p - (long)x * PXS);
                int y = rem / PYS, z = rem - y * PYS;
                bool valid = (x >= 1) && (x <= 64) && (y >= 1) && (y <= 64)
                             && (z >= 1) && (z <= 64);
                if (!valid) continue;   // pads of g_Q must stay zero
            }
            long base = (GUARD + p) * 64;
#pragma unroll
            for (int nt = 0; nt < 8; ++nt) {
                int col = nt * 8 + tig * 2;
                float v0r = fmaxf(acc[mt][nt][half * 2 + 0] + s_ep[col], 0.f)
                            * s_ep[64 + col] + s_ep[128 + col];
                float v1r = fmaxf(acc[mt][nt][half * 2 + 1] + s_ep[col + 1], 0.f)
                            * s_ep[64 + col + 1] + s_ep[128 + col + 1];
                __half2 hv;
                hv.x = __float2half_rn(v0r);
                hv.y = __float2half_rn(v1r);
                if (STAGE == 1) *(__half2*)&g_Q[base + col]   = hv;
                else            *(__half2*)&g_h2p[base + col] = hv;
            }
        }
}

// ---------------------------------------------------------------------------
// devoxelize: trilinear gather from fp16 g_h2p + residual add of g_mlp.
// ---------------------------------------------------------------------------
__global__ void gather_kernel(const float* __restrict__ coords,
                              float* __restrict__ out)
{
    int t = blockIdx.x * blockDim.x + threadIdx.x;
    if (t >= N_PTS * 32) return;
    int n = t >> 5, c2 = (t & 31) << 1;

    float px = fminf(fmaxf(coords[n * 3 + 0], 0.f), 63.f);
    float py = fminf(fmaxf(coords[n * 3 + 1], 0.f), 63.f);
    float pz = fminf(fmaxf(coords[n * 3 + 2], 0.f), 63.f);
    float fx = floorf(px), fy = floorf(py), fz = floorf(pz);
    int x0 = (int)fx, y0 = (int)fy, z0 = (int)fz;
    int x1 = min(x0 + 1, 63), y1 = min(y0 + 1, 63), z1 = min(z0 + 1, 63);
    float tx = px - fx, ty = py - fy, tz = pz - fz;

    auto at = [&](int x, int y, int z) {
        long row = (long)GUARD + (long)(x + 1) * PXS + (y + 1) * PYS + (z + 1);
        __half2 h = *(const __half2*)&g_h2p[row * 64 + c2];
        return __half22float2(h);
    };
    float2 r = *(const float2*)&g_mlp[n * 64 + c2];
    float2 f;
    float w;
    w = (1.f - tx) * (1.f - ty) * (1.f - tz); f = at(x0, y0, z0); r.x += w * f.x; r.y += w * f.y;
    w = (1.f - tx) * (1.f - ty) * tz;          f = at(x0, y0, z1); r.x += w * f.x; r.y += w * f.y;
    w = (1.f - tx) * ty          * (1.f - tz); f = at(x0, y1, z0); r.x += w * f.x; r.y += w * f.y;
    w = (1.f - tx) * ty          * tz;          f = at(x0, y1, z1); r.x += w * f.x; r.y += w * f.y;
    w = tx          * (1.f - ty) * (1.f - tz); f = at(x1, y0, z0); r.x += w * f.x; r.y += w * f.y;
    w = tx          * (1.f - ty) * tz;          f = at(x1, y0, z1); r.x += w * f.x; r.y += w * f.y;
    w = tx          * ty          * (1.f - tz); f = at(x1, y1, z0); r.x += w * f.x; r.y += w * f.y;
    w = tx          * ty          * tz;          f = at(x1, y1, z1); r.x += w * f.x; r.y += w * f.y;

    *(float2*)&out[n * 64 + c2] = r;
}

// ---------------------------------------------------------------------------
extern "C" void kernel_launch(void* const* d_in, const int* in_sizes, int n_in,
                              void* d_out, int out_size)
{
    const float* inputs    = (const float*)d_in[0];
    const float* pt_coords = (const float*)d_in[1];
    const int*   vidx      = (const int*)  d_in[2];
    const float* pinv      = (const float*)d_in[3];
    const float* w_mlp     = (const float*)d_in[4];
    const float* b_mlp     = (const float*)d_in[5];
    const float* g0        = (const float*)d_in[6];
    const float* be0       = (const float*)d_in[7];
    const float* m0        = (const float*)d_in[8];
    const float* v0        = (const float*)d_in[9];
    const float* k1        = (const float*)d_in[10];
    const float* cb1       = (const float*)d_in[11];
    const float* g1        = (const float*)d_in[12];
    const float* be1       = (const float*)d_in[13];
    const float* m1        = (const float*)d_in[14];
    const float* v1        = (const float*)d_in[15];
    const float* k2        = (const float*)d_in[16];
    const float* cb2       = (const float*)d_in[17];
    const float* g2        = (const float*)d_in[18];
    const float* be2       = (const float*)d_in[19];
    const float* m2        = (const float*)d_in[20];
    const float* v2        = (const float*)d_in[21];
    float* out = (float*)d_out;

    // one-time host-side resource setup (no device memory involved)
    static cudaStream_t s2 = nullptr;
    static cudaEvent_t evFork = nullptr, evJoin = nullptr;
    static cudaEvent_t evC1 = nullptr, evZ = nullptr, evW = nullptr;
    if (s2 == nullptr) {
        cudaStreamCreateWithFlags(&s2, cudaStreamNonBlocking);
        cudaEventCreateWithFlags(&evFork, cudaEventDisableTiming);
        cudaEventCreateWithFlags(&evJoin, cudaEventDisableTiming);
        cudaEventCreateWithFlags(&evC1, cudaEventDisableTiming);
        cudaEventCreateWithFlags(&evZ, cudaEventDisableTiming);
        cudaEventCreateWithFlags(&evW, cudaEventDisableTiming);
    }

    const int DSMEM_MLP = 24576;
    cudaFuncSetAttribute(conv_mma_kernel<1>,
                         cudaFuncAttributeMaxDynamicSharedMemorySize, DSMEM_CONV);
    cudaFuncSetAttribute(conv_mma_kernel<2>,
                         cudaFuncAttributeMaxDynamicSharedMemorySize, DSMEM_CONV);
    cudaFuncSetAttribute(mlp_mma_kernel,
                         cudaFuncAttributeMaxDynamicSharedMemorySize, DSMEM_MLP);

    cudaEventRecord(evFork, 0);
    cudaStreamWaitEvent(s2, evFork, 0);

    // main stream: scatter (fused voxelize+scale)
    scatter_kernel<<<(N_PTS * 32 + 255) / 256, 256>>>(inputs, vidx, pinv);

    // s2: weight prep first (cheap), then the point branch
    build_W_kernel<<<(2 * 27 * 64 * 64 + 255) / 256, 256, 0, s2>>>(k1, k2);
    cudaEventRecord(evW, s2);
    mlp_mma_kernel<<<NTILE_M, 256, DSMEM_MLP, s2>>>(inputs, w_mlp, b_mlp,
                                                    g0, be0, m0, v0);
    cudaEventRecord(evJoin, s2);

    // conv1 needs g_W (ready long before scatter finishes)
    cudaStreamWaitEvent(0, evW, 0);
    conv_mma_kernel<1><<<NTILE2, 256, DSMEM_CONV>>>(cb1, g1, be1, m1, v1);
    cudaEventRecord(evC1, 0);

    // s2: re-zero g_P for the next replay, concurrent with conv2
    cudaStreamWaitEvent(s2, evC1, 0);
    zero_P_kernel<<<2048, 256, 0, s2>>>();
    cudaEventRecord(evZ, s2);

    conv_mma_kernel<2><<<NTILE2, 256, DSMEM_CONV>>>(cb2, g2, be2, m2, v2);

    // join: gather needs conv2 (stream 0), mlp and zero_P (s2)
    cudaStreamWaitEvent(0, evJoin, 0);
    cudaStreamWaitEvent(0, evZ, 0);
    gather_kernel<<<(N_PTS * 32 + 255) / 256, 256>>>(pt_coords, out);
}

// round 16
// speedup vs baseline: 1.0267x; 1.0267x over previous
#include <cuda_runtime.h>
#include <cuda_fp16.h>
#include <cstdint>

#define N_PTS 200000

// x-compact padded grid: 64 x-slices of 66x66 (y,z padded), GUARD provides
// the x-direction zero pads. Every tap-shifted window stays in-bounds.
#define PXS 4356            // x stride (66*66)
#define PYS 66              // y stride
#define PTOT 278784         // 64 * 66 * 66
#define GUARD 4800
#define PROWS (PTOT + 2*GUARD)   // 288384
#define MTILE 512
#define NTILE2 545          // ceil(PTOT/512)
#define NTILE_M 1563        // ceil(N_PTS/128)

// conv smem: A window 646 rows x 128B (x2), W 3 taps x 8KB (x2)
#define AROWS 646
#define ABYTES (AROWS*128)                  // 82688
#define WBYTES (3*8192)                     // 24576
#define SMEM_W0 (2*ABYTES)                  // 165376
#define DSMEM_CONV (2*ABYTES + 2*WBYTES)    // 214528

// ---- scratch (allocation-free: __device__ globals, zero-initialized) ----
__device__ __half g_P[PROWS*64];          // conv1 input fp16: scatter target
                                          // (pre-scaled by pinv; pads stay 0)
__device__ __half g_Q[PROWS*64];          // conv2 input fp16 (pads stay 0)
__device__ __half g_h2p[PROWS*64];        // conv2 output fp16, padded
__device__ float g_mlp[N_PTS*64];         // point branch
__device__ __half g_W[2][27*64*64];       // weights [tap][cout][cin] fp16

// ---------------------------------------------------------------------------
// helpers
// ---------------------------------------------------------------------------
__device__ __forceinline__ uint32_t smem_u32(const void* p) {
    uint32_t a;
    asm("{ .reg .u64 t; cvta.to.shared.u64 t, %1; cvt.u32.u64 %0, t; }"
        : "=r"(a) : "l"(p));
    return a;
}
__device__ __forceinline__ void ldsm_x4(uint32_t* r, uint32_t a) {
    asm volatile("ldmatrix.sync.aligned.m8n8.x4.shared.b16 {%0,%1,%2,%3}, [%4];"
        : "=r"(r[0]), "=r"(r[1]), "=r"(r[2]), "=r"(r[3]) : "r"(a));
}
__device__ __forceinline__ void ldsm_x2(uint32_t* r, uint32_t a) {
    asm volatile("ldmatrix.sync.aligned.m8n8.x2.shared.b16 {%0,%1}, [%2];"
        : "=r"(r[0]), "=r"(r[1]) : "r"(a));
}
__device__ __forceinline__ void mma_f16(float* c, const uint32_t* a,
                                        const uint32_t* b) {
    asm volatile("mma.sync.aligned.m16n8k16.row.col.f32.f16.f16.f32 "
        "{%0,%1,%2,%3}, {%4,%5,%6,%7}, {%8,%9}, {%0,%1,%2,%3};"
        : "+f"(c[0]), "+f"(c[1]), "+f"(c[2]), "+f"(c[3])
        : "r"(a[0]), "r"(a[1]), "r"(a[2]), "r"(a[3]), "r"(b[0]), "r"(b[1]));
}
#define CP_ASYNC16(dst, src) \
    asm volatile("cp.async.cg.shared.global [%0], [%1], 16;" \
        :: "r"(dst), "l"(src) : "memory")
#define CP_COMMIT() asm volatile("cp.async.commit_group;" ::: "memory")
#define CP_WAIT(n)  asm volatile("cp.async.wait_group %0;" :: "n"(n) : "memory")

// ---------------------------------------------------------------------------
// voxelize fused: atomicAdd half2 of (in * pinv) directly into padded g_P.
// ---------------------------------------------------------------------------
__global__ void scatter_kernel(const float* __restrict__ in,
                               const int* __restrict__ vidx,
                               const float* __restrict__ pinv)
{
    int t = blockIdx.x * blockDim.x + threadIdx.x;
    if (t >= N_PTS * 32) return;
    int n = t >> 5, c2 = t & 31;
    int ix = vidx[n * 3 + 0];
    int iy = vidx[n * 3 + 1];
    int iz = vidx[n * 3 + 2];
    int vox = (((ix << 6) + iy) << 6) + iz;
    float s = pinv[vox];
    float2 v = ((const float2*)in)[n * 32 + c2];
    __half2 h;
    h.x = __float2half_rn(v.x * s);
    h.y = __float2half_rn(v.y * s);
    long p = (long)ix * PXS + (iy + 1) * PYS + (iz + 1);
    atomicAdd((__half2*)&g_P[(GUARD + p) * 64 + c2 * 2], h);
}

// ---------------------------------------------------------------------------
// re-zero g_P's real-voxel region for the next graph replay
// ---------------------------------------------------------------------------
__global__ void zero_P_kernel() {
    float4* p = (float4*)&g_P[(long)GUARD * 64];
    const long n4 = (long)PTOT * 64 / 8;   // halfs -> float4 units
    for (long i = blockIdx.x * blockDim.x + threadIdx.x; i < n4;
         i += (long)gridDim.x * blockDim.x)
        p[i] = make_float4(0.f, 0.f, 0.f, 0.f);
}

// ---------------------------------------------------------------------------
// weight prep (both conv stages in one launch):
// k [tap][cin][cout] fp32 -> [tap][cout][cin] fp16
// ---------------------------------------------------------------------------
__global__ void build_W_kernel(const float* __restrict__ k1,
                               const float* __restrict__ k2) {
    int i = blockIdx.x * blockDim.x + threadIdx.x;
    const int n = 27 * 64 * 64;
    if (i >= 2 * n) return;
    int stage = (i >= n);
    int j = i - stage * n;
    const float* k = stage ? k2 : k1;
    int tap = j >> 12, r = j & 4095, cin = r >> 6, cout = r & 63;
    g_W[stage][(tap << 12) + (cout << 6) + cin] = __float2half_rn(k[j]);
}

// ---------------------------------------------------------------------------
// MLP as fp16 mma GEMM: CTA = 128 points x 64 couts, 8 warps (32x32 tiles)
// ---------------------------------------------------------------------------
__global__ __launch_bounds__(256) void mlp_mma_kernel(
    const float* __restrict__ in, const float* __restrict__ w,
    const float* __restrict__ b,
    const float* __restrict__ g0, const float* __restrict__ be0,
    const float* __restrict__ m0v, const float* __restrict__ v0)
{
    extern __shared__ char dyn[];
    __shared__ float s_ep[192];
    const int tid = threadIdx.x, lane = tid & 31, warp = tid >> 5;
    const int m0 = (warp >> 1) * 32, n0 = (warp & 1) * 32;
    const uint32_t S0 = smem_u32(dyn);

    if (tid < 64) {
        float sc = g0[tid] * rsqrtf(v0[tid] + 1e-3f);
        s_ep[tid] = b[tid];
        s_ep[64 + tid] = sc;
        s_ep[128 + tid] = be0[tid] - m0v[tid] * sc;
    }

    const float4* in4 = (const float4*)in;
    for (int i = tid; i < 2048; i += 256) {
        int row = i >> 4, c = i & 15;
        long n = (long)blockIdx.x * 128 + row;
        __half2 h0, h1;
        h0.x = h0.y = h1.x = h1.y = __float2half_rn(0.f);
        if (n < N_PTS) {
            float4 raw = in4[n * 16 + c];
            h0.x = __float2half_rn(raw.x); h0.y = __float2half_rn(raw.y);
            h1.x = __float2half_rn(raw.z); h1.y = __float2half_rn(raw.w);
        }
        uint32_t d = row * 128 + ((((uint32_t)(c >> 1)) ^ (row & 7)) << 4)
                     + (c & 1) * 8;
        *(__half2*)(dyn + d)     = h0;
        *(__half2*)(dyn + d + 4) = h1;
    }
    for (int i = tid; i < 4096; i += 256) {
        int ci = i >> 6, co = i & 63;
        uint32_t d = co * 128 + ((((uint32_t)(ci >> 3)) ^ (co & 7)) << 4)
                     + (ci & 7) * 2;
        *(__half*)(dyn + 16384 + d) = __float2half_rn(w[i]);
    }
    __syncthreads();

    float acc[2][4][4];
#pragma unroll
    for (int a = 0; a < 2; ++a)
#pragma unroll
        for (int x = 0; x < 4; ++x)
#pragma unroll
            for (int c = 0; c < 4; ++c) acc[a][x][c] = 0.f;

    const int arow = lane & 15, asel = lane >> 4;
    const int brow = lane & 7, bsel = (lane >> 3) & 1;
#pragma unroll
    for (int kc = 0; kc < 4; ++kc) {
        uint32_t af[2][4], bf[4][2];
#pragma unroll
        for (int mt = 0; mt < 2; ++mt) {
            int row = m0 + mt * 16 + arow;
            ldsm_x4(af[mt], S0 + row * 128 +
                    (((uint32_t)((kc * 2 + asel) ^ (row & 7))) << 4));
        }
#pragma unroll
        for (int nt = 0; nt < 4; ++nt) {
            int row = n0 + nt * 8 + brow;
            ldsm_x2(bf[nt], S0 + 16384 + row * 128 +
                    (((uint32_t)((kc * 2 + bsel) ^ (row & 7))) << 4));
        }
#pragma unroll
        for (int mt = 0; mt < 2; ++mt)
#pragma unroll
            for (int nt = 0; nt < 4; ++nt)
                mma_f16(acc[mt][nt], af[mt], bf[nt]);
    }

    const int gr = lane >> 2, tig = lane & 3;
#pragma unroll
    for (int mt = 0; mt < 2; ++mt)
#pragma unroll
        for (int half = 0; half < 2; ++half) {
            long n = (long)blockIdx.x * 128 + m0 + mt * 16 + half * 8 + gr;
            if (n >= N_PTS) continue;
#pragma unroll
            for (int nt = 0; nt < 4; ++nt) {
                int col = n0 + nt * 8 + tig * 2;
                float v0r = fmaxf(acc[mt][nt][half * 2 + 0] + s_ep[col], 0.f)
                            * s_ep[64 + col] + s_ep[128 + col];
                float v1r = fmaxf(acc[mt][nt][half * 2 + 1] + s_ep[col + 1], 0.f)
                            * s_ep[64 + col + 1] + s_ep[128 + col + 1];
                float2 fv; fv.x = v0r; fv.y = v1r;
                *(float2*)&g_mlp[n * 64 + col] = fv;
            }
        }
}

// ---------------------------------------------------------------------------
// Pipelined fp16 mma implicit-GEMM conv.
// CTA = 512 padded rows x 64 couts, 8 warps, warp tile 64x64.
// A window (646 rows: MTILE + 2*PYS + 2 halo) staged once per dx (3 stages);
// dy/dz taps are served from in-smem row offsets dy*66+dz. W staged per
// (dx,dy) group (9 stages of 3 taps). Both cp.async double-buffered with a
// single barrier per ws-stage. Fragment double-buffering hides ldsm latency.
// smem: A[0, 2*82688), W[165376, +2*24576)
// ---------------------------------------------------------------------------
template<int STAGE>
__device__ __forceinline__ void stage_A_async(
    uint32_t Sbuf, const __half* __restrict__ SRC, long blockbase,
    int dx, int tid)
{
    const long w0 = (long)GUARD + blockbase
                    + (long)(dx - 1) * PXS - PYS - 1;
    const uint4* asrc = (const uint4*)SRC + w0 * 8;
    for (int i = tid; i < AROWS * 8; i += 256) {
        int row = i >> 3, c = i & 7;
        uint32_t d = Sbuf + row * 128 + (((uint32_t)(c ^ (row & 7))) << 4);
        CP_ASYNC16(d, asrc + i);
    }
}
__device__ __forceinline__ void stage_W_async(
    uint32_t Sbuf, const uint4* __restrict__ Wsrc, int ws, int tid)
{
    const int tap0 = ws * 3;
    for (int i = tid; i < 1536; i += 256) {
        int t3 = i >> 9, r = (i >> 3) & 63, c = i & 7;
        uint32_t d = Sbuf + t3 * 8192 + r * 128 +
                     (((uint32_t)(c ^ (r & 7))) << 4);
        CP_ASYNC16(d, Wsrc + (tap0 + t3) * 512 + r * 8 + c);
    }
}

template<int STAGE>
__global__ __launch_bounds__(256, 1) void conv_mma_kernel(
    const float* __restrict__ cb, const float* __restrict__ g,
    const float* __restrict__ be, const float* __restrict__ m,
    const float* __restrict__ v)
{
    extern __shared__ char dyn[];
    __shared__ float s_ep[192];
    const int tid = threadIdx.x, lane = tid & 31, warp = tid >> 5;
    const int m0 = warp * 64;   // 8 m-groups of 64 rows, full 64 couts
    const uint32_t S0 = smem_u32(dyn);
    const uint32_t SWB = S0 + SMEM_W0;

    if (tid < 64) {
        float sc = g[tid] * rsqrtf(v[tid] + 1e-3f);
        s_ep[tid] = cb[tid];
        s_ep[64 + tid] = sc;
        s_ep[128 + tid] = be[tid] - m[tid] * sc;
    }

    const __half* __restrict__ SRC = (STAGE == 1) ? g_P : g_Q;
    const uint4* __restrict__ Wsrc = (const uint4*)g_W[STAGE - 1];
    const long blockbase = (long)blockIdx.x * MTILE;

    float acc[4][8][4];
#pragma unroll
    for (int a = 0; a < 4; ++a)
#pragma unroll
        for (int x = 0; x < 8; ++x)
#pragma unroll
            for (int c = 0; c < 4; ++c) acc[a][x][c] = 0.f;

    const int arow = lane & 15, asel = lane >> 4;
    const int bq = lane >> 3;
    const int bnt_off = bq >> 1;
    const int bks = bq & 1;
    const int brow8 = lane & 7;

    // prologue: A window for dx=0 + W group 0
    stage_A_async<STAGE>(S0, SRC, blockbase, 0, tid);
    stage_W_async(SWB, Wsrc, 0, tid);
    CP_COMMIT();

    uint32_t afb[2][4][4], bfb[2][8][2];

    for (int ws = 0; ws < 9; ++ws) {
        const int dx = ws / 3, dy = ws % 3;
        CP_WAIT(0);          // everything committed so far has landed
        __syncthreads();     // publish; free buffers being overwritten next
        if (ws < 8) {
            stage_W_async(SWB + ((ws + 1) & 1) * WBYTES, Wsrc, ws + 1, tid);
            if (dy == 0 && dx < 2)
                stage_A_async<STAGE>(S0 + ((dx + 1) & 1) * ABYTES, SRC,
                                     blockbase, dx + 1, tid);
            CP_COMMIT();
        }

        const uint32_t SA = S0 + (dx & 1) * ABYTES;
        const uint32_t SW = SWB + (ws & 1) * WBYTES;
        const int rowbase = dy * PYS;   // dy shift inside the A window

        // prologue fragment load: iteration 0 (dz=0, kc=0)
#pragma unroll
        for (int mt = 0; mt < 4; ++mt) {
            int row = rowbase + m0 + mt * 16 + arow;
            ldsm_x4(afb[0][mt], SA + row * 128 +
                    (((uint32_t)((0 * 2 + asel) ^ (row & 7))) << 4));
        }
#pragma unroll
        for (int np = 0; np < 4; ++np) {
            int row = (np * 2 + bnt_off) * 8 + brow8;
            ldsm_x4(&bfb[0][np * 2][0], SW + 0 * 8192 + row * 128 +
                    (((uint32_t)((0 * 2 + bks) ^ (row & 7))) << 4));
        }

#pragma unroll
        for (int it = 0; it < 12; ++it) {
            const int cur = it & 1;
            if (it < 11) {
                const int nit = it + 1;
                const int ndz = nit >> 2, nkc = nit & 3;
                const int nxt = nit & 1;
#pragma unroll
                for (int mt = 0; mt < 4; ++mt) {
                    int row = rowbase + ndz + m0 + mt * 16 + arow;
                    ldsm_x4(afb[nxt][mt], SA + row * 128 +
                            (((uint32_t)((nkc * 2 + asel) ^ (row & 7))) << 4));
                }
#pragma unroll
                for (int np = 0; np < 4; ++np) {
                    int row = (np * 2 + bnt_off) * 8 + brow8;
                    ldsm_x4(&bfb[nxt][np * 2][0], SW + ndz * 8192 + row * 128 +
                            (((uint32_t)((nkc * 2 + bks) ^ (row & 7))) << 4));
                }
            }
#pragma unroll
            for (int mt = 0; mt < 4; ++mt)
#pragma unroll
                for (int nt = 0; nt < 8; ++nt)
                    mma_f16(acc[mt][nt], afb[cur][mt], bfb[cur][nt]);
        }
    }

    // ---- epilogue: bias + relu + BN ----
    const int gr = lane >> 2, tig = lane & 3;
#pragma unroll
    for (int mt = 0; mt < 4; ++mt)
#pragma unroll
        for (int half = 0; half < 2; ++half) {
            int rl = m0 + mt * 16 + half * 8 + gr;
            long p = blockbase + rl;
            if (p >= PTOT) continue;
            if (STAGE == 1) {
                int rem = (int)(p % PXS);
                int y = rem / PYS, z = rem - y * PYS;
                bool valid = (y >= 1) && (y <= 64) && (z >= 1) && (z <= 64);
                if (!valid) continue;   // pads of g_Q must stay zero
            }
            long base = (GUARD + p) * 64;
#pragma unroll
            for (int nt = 0; nt < 8; ++nt) {
                int col = nt * 8 + tig * 2;
                float v0r = fmaxf(acc[mt][nt][half * 2 + 0] + s_ep[col], 0.f)
                            * s_ep[64 + col] + s_ep[128 + col];
                float v1r = fmaxf(acc[mt][nt][half * 2 + 1] + s_ep[col + 1], 0.f)
                            * s_ep[64 + col + 1] + s_ep[128 + col + 1];
                __half2 hv;
                hv.x = __float2half_rn(v0r);
                hv.y = __float2half_rn(v1r);
                if (STAGE == 1) *(__half2*)&g_Q[base + col]   = hv;
                else            *(__half2*)&g_h2p[base + col] = hv;
            }
        }
}

// ---------------------------------------------------------------------------
// devoxelize: trilinear gather from fp16 g_h2p + residual add of g_mlp.
// ---------------------------------------------------------------------------
__global__ void gather_kernel(const float* __restrict__ coords,
                              float* __restrict__ out)
{
    int t = blockIdx.x * blockDim.x + threadIdx.x;
    if (t >= N_PTS * 32) return;
    int n = t >> 5, c2 = (t & 31) << 1;

    float px = fminf(fmaxf(coords[n * 3 + 0], 0.f), 63.f);
    float py = fminf(fmaxf(coords[n * 3 + 1], 0.f), 63.f);
    float pz = fminf(fmaxf(coords[n * 3 + 2], 0.f), 63.f);
    float fx = floorf(px), fy = floorf(py), fz = floorf(pz);
    int x0 = (int)fx, y0 = (int)fy, z0 = (int)fz;
    int x1 = min(x0 + 1, 63), y1 = min(y0 + 1, 63), z1 = min(z0 + 1, 63);
    float tx = px - fx, ty = py - fy, tz = pz - fz;

    auto at = [&](int x, int y, int z) {
        long row = (long)GUARD + (long)x * PXS + (y + 1) * PYS + (z + 1);
        __half2 h = *(const __half2*)&g_h2p[row * 64 + c2];
        return __half22float2(h);
    };
    float2 r = *(const float2*)&g_mlp[n * 64 + c2];
    float2 f;
    float w;
    w = (1.f - tx) * (1.f - ty) * (1.f - tz); f = at(x0, y0, z0); r.x += w * f.x; r.y += w * f.y;
    w = (1.f - tx) * (1.f - ty) * tz;          f = at(x0, y0, z1); r.x += w * f.x; r.y += w * f.y;
    w = (1.f - tx) * ty          * (1.f - tz); f = at(x0, y1, z0); r.x += w * f.x; r.y += w * f.y;
    w = (1.f - tx) * ty          * tz;          f = at(x0, y1, z1); r.x += w * f.x; r.y += w * f.y;
    w = tx          * (1.f - ty) * (1.f - tz); f = at(x1, y0, z0); r.x += w * f.x; r.y += w * f.y;
    w = tx          * (1.f - ty) * tz;          f = at(x1, y0, z1); r.x += w * f.x; r.y += w * f.y;
    w = tx          * ty          * (1.f - tz); f = at(x1, y1, z0); r.x += w * f.x; r.y += w * f.y;
    w = tx          * ty          * tz;          f = at(x1, y1, z1); r.x += w * f.x; r.y += w * f.y;

    *(float2*)&out[n * 64 + c2] = r;
}

// ---------------------------------------------------------------------------
extern "C" void kernel_launch(void* const* d_in, const int* in_sizes, int n_in,
                              void* d_out, int out_size)
{
    const float* inputs    = (const float*)d_in[0];
    const float* pt_coords = (const float*)d_in[1];
    const int*   vidx      = (const int*)  d_in[2];
    const float* pinv      = (const float*)d_in[3];
    const float* w_mlp     = (const float*)d_in[4];
    const float* b_mlp     = (const float*)d_in[5];
    const float* g0        = (const float*)d_in[6];
    const float* be0       = (const float*)d_in[7];
    const float* m0        = (const float*)d_in[8];
    const float* v0        = (const float*)d_in[9];
    const float* k1        = (const float*)d_in[10];
    const float* cb1       = (const float*)d_in[11];
    const float* g1        = (const float*)d_in[12];
    const float* be1       = (const float*)d_in[13];
    const float* m1        = (const float*)d_in[14];
    const float* v1        = (const float*)d_in[15];
    const float* k2        = (const float*)d_in[16];
    const float* cb2       = (const float*)d_in[17];
    const float* g2        = (const float*)d_in[18];
    const float* be2       = (const float*)d_in[19];
    const float* m2        = (const float*)d_in[20];
    const float* v2        = (const float*)d_in[21];
    float* out = (float*)d_out;

    // one-time host-side resource setup (no device memory involved)
    static cudaStream_t s2 = nullptr;
    static cudaEvent_t evFork = nullptr, evJoin = nullptr;
    static cudaEvent_t evC1 = nullptr, evZ = nullptr, evW = nullptr;
    if (s2 == nullptr) {
        cudaStreamCreateWithFlags(&s2, cudaStreamNonBlocking);
        cudaEventCreateWithFlags(&evFork, cudaEventDisableTiming);
        cudaEventCreateWithFlags(&evJoin, cudaEventDisableTiming);
        cudaEventCreateWithFlags(&evC1, cudaEventDisableTiming);
        cudaEventCreateWithFlags(&evZ, cudaEventDisableTiming);
        cudaEventCreateWithFlags(&evW, cudaEventDisableTiming);
    }

    const int DSMEM_MLP = 24576;
    cudaFuncSetAttribute(conv_mma_kernel<1>,
                         cudaFuncAttributeMaxDynamicSharedMemorySize, DSMEM_CONV);
    cudaFuncSetAttribute(conv_mma_kernel<2>,
                         cudaFuncAttributeMaxDynamicSharedMemorySize, DSMEM_CONV);
    cudaFuncSetAttribute(mlp_mma_kernel,
                         cudaFuncAttributeMaxDynamicSharedMemorySize, DSMEM_MLP);

    cudaEventRecord(evFork, 0);
    cudaStreamWaitEvent(s2, evFork, 0);

    // main stream: scatter (fused voxelize+scale)
    scatter_kernel<<<(N_PTS * 32 + 255) / 256, 256>>>(inputs, vidx, pinv);

    // s2: weight prep first (cheap), then the point branch
    build_W_kernel<<<(2 * 27 * 64 * 64 + 255) / 256, 256, 0, s2>>>(k1, k2);
    cudaEventRecord(evW, s2);
    mlp_mma_kernel<<<NTILE_M, 256, DSMEM_MLP, s2>>>(inputs, w_mlp, b_mlp,
                                                    g0, be0, m0, v0);
    cudaEventRecord(evJoin, s2);

    // conv1 needs g_W (ready long before scatter finishes)
    cudaStreamWaitEvent(0, evW, 0);
    conv_mma_kernel<1><<<NTILE2, 256, DSMEM_CONV>>>(cb1, g1, be1, m1, v1);
    cudaEventRecord(evC1, 0);

    // s2: re-zero g_P for the next replay, concurrent with conv2
    cudaStreamWaitEvent(s2, evC1, 0);
    zero_P_kernel<<<2048, 256, 0, s2>>>();
    cudaEventRecord(evZ, s2);

    conv_mma_kernel<2><<<NTILE2, 256, DSMEM_CONV>>>(cb2, g2, be2, m2, v2);

    // join: gather needs conv2 (stream 0), mlp and zero_P (s2)
    cudaStreamWaitEvent(0, evJoin, 0);
    cudaStreamWaitEvent(0, evZ, 0);
    gather_kernel<<<(N_PTS * 32 + 255) / 256, 256>>>(pt_coords, out);
}